// round 15
// baseline (speedup 1.0000x reference)
#include <cuda_runtime.h>
#include <cuda_bf16.h>
#include <math.h>
#include <cstdint>

// Problem dims
#define B_   64
#define DV_  2048
#define WH_  196
#define DQ_  2400
#define DA_  1200
#define G_   2
#define DH_  1200
#define NC_  3000
#define MROWS (B_*WH_)   // 12544
#define NBLK_N 10        // DA_/128 column blocks in gemm1
#define NT_G1 (NBLK_N * (MROWS/128))   // 980 gemm1 tiles
#define NB_QF (38 * 8)                 // qfus co-scheduled blocks

// ---------------- scratch (device globals; no allocation allowed) ----------
__device__ float g_wgtp[NBLK_N * MROWS * G_];   // wgt partials
__device__ float g_xq  [B_ * DA_];
__device__ float g_att [B_ * G_ * WH_];
__device__ float g_vatt[B_ * G_ * DV_];
__device__ float g_hfus[B_ * G_ * DH_];
__device__ float g_part[2 * 8 * 64 * NC_];      // split-K partials, carved:
#define P_XQ 0L                                  //  xq:   8*64*1200
#define P_QF (8L * 64 * 1200)                    //  qfus: 8*64*2400
#define P_VF (P_QF + 8L * 64 * 2400)             //  vfus: 16*64*1200
// final gemm reuses offset 0 (xq+qfus dead by then)
// bf16 split operands for GEMM1 (A = V transposed to [M,K] K-major)
__device__ __nv_bfloat16 g_Ahi[(size_t)MROWS * DV_];
__device__ __nv_bfloat16 g_Alo[(size_t)MROWS * DV_];
__device__ __nv_bfloat16 g_Bhi[(size_t)DA_ * DV_];
__device__ __nv_bfloat16 g_Blo[(size_t)DA_ * DV_];

// ============================ PTX helpers ==================================
__device__ __forceinline__ uint32_t smem_u32(const void* p) {
    uint32_t a;
    asm("{ .reg .u64 t; cvta.to.shared.u64 t, %1; cvt.u32.u64 %0, t; }" : "=r"(a) : "l"(p));
    return a;
}
__device__ __forceinline__ void cp16(uint32_t dst, const void* src) {
    asm volatile("cp.async.cg.shared.global [%0], [%1], 16;" :: "r"(dst), "l"(src));
}
#define CP_COMMIT() asm volatile("cp.async.commit_group;" ::: "memory")
#define CP_WAIT(n)  asm volatile("cp.async.wait_group %0;" :: "n"(n) : "memory")

__device__ __forceinline__ void ldsm_x4(uint32_t* r, uint32_t addr) {
    asm volatile("ldmatrix.sync.aligned.m8n8.x4.shared.b16 {%0,%1,%2,%3}, [%4];"
                 : "=r"(r[0]), "=r"(r[1]), "=r"(r[2]), "=r"(r[3]) : "r"(addr));
}
__device__ __forceinline__ void mma_bf16(float* c, const uint32_t* a, const uint32_t* b) {
    asm volatile("mma.sync.aligned.m16n8k16.row.col.f32.bf16.bf16.f32 "
                 "{%0,%1,%2,%3}, {%4,%5,%6,%7}, {%8,%9}, {%0,%1,%2,%3};"
                 : "+f"(c[0]), "+f"(c[1]), "+f"(c[2]), "+f"(c[3])
                 : "r"(a[0]), "r"(a[1]), "r"(a[2]), "r"(a[3]), "r"(b[0]), "r"(b[1]));
}
#define SWZ(bo) ((bo) ^ (((bo) >> 3) & 0x70))

__device__ __forceinline__ void split_bf16(float x, __nv_bfloat16& hi, __nv_bfloat16& lo) {
    hi = __float2bfloat16(x);
    lo = __float2bfloat16(x - __bfloat162float(hi));
}

// ============================ shared small-GEMM body =======================
// Split-K fp32 GEMM slice (M=64 exactly): 64x64 tile, BK=32, 256 threads,
// 4x4/thread, depth-2 register prefetch. Writes raw partials.
__device__ __forceinline__ void gemm64_body(
    const float* __restrict__ A, const float* __restrict__ W,
    float* __restrict__ part,      // pre-offset by g if batched
    int Ntot, int K, int lda,
    int n0, int split, int SPLITS,
    float (*As)[33], float (*Bs)[33])
{
    const int tid = threadIdx.x;
    const int ty  = tid >> 4;
    const int tx  = tid & 15;
    const int lr  = tid >> 5;
    const int lk  = tid & 31;

    const int stages   = K / 32;
    const int st_begin = (stages * split) / SPLITS;
    const int st_end   = (stages * (split + 1)) / SPLITS;
    const int nst      = st_end - st_begin;

    auto fetchA = [&](int st, float* r) {
        int k0 = st * 32;
#pragma unroll
        for (int i = 0; i < 8; i++)
            r[i] = A[(long)(i * 8 + lr) * lda + k0 + lk];
    };
    auto fetchB = [&](int st, float* r) {
        int k0 = st * 32;
#pragma unroll
        for (int i = 0; i < 8; i++) {
            int ng = n0 + i * 8 + lr; if (ng >= Ntot) ng = Ntot - 1;
            r[i] = W[(long)ng * K + k0 + lk];
        }
    };

    float rA[2][8], rB[2][8];
    fetchA(st_begin, rA[0]); fetchB(st_begin, rB[0]);
    if (nst > 1) { fetchA(st_begin + 1, rA[1]); fetchB(st_begin + 1, rB[1]); }

    float acc[4][4];
#pragma unroll
    for (int i = 0; i < 4; i++)
#pragma unroll
        for (int j = 0; j < 4; j++) acc[i][j] = 0.f;

    for (int s = 0; s < nst; s++) {
        float* cA = rA[s & 1];
        float* cB = rB[s & 1];
        __syncthreads();
#pragma unroll
        for (int i = 0; i < 8; i++) {
            As[i * 8 + lr][lk] = cA[i];
            Bs[i * 8 + lr][lk] = cB[i];
        }
        if (s + 2 < nst) { fetchA(st_begin + s + 2, cA); fetchB(st_begin + s + 2, cB); }
        __syncthreads();
#pragma unroll
        for (int kk = 0; kk < 32; kk++) {
            float a[4], b[4];
#pragma unroll
            for (int i = 0; i < 4; i++) a[i] = As[ty * 4 + i][kk];
#pragma unroll
            for (int j = 0; j < 4; j++) b[j] = Bs[tx * 4 + j][kk];
#pragma unroll
            for (int i = 0; i < 4; i++)
#pragma unroll
                for (int j = 0; j < 4; j++) acc[i][j] += a[i] * b[j];
        }
    }

    float* pbase = part + ((long)split * 64) * Ntot;
#pragma unroll
    for (int i = 0; i < 4; i++) {
        int m = ty * 4 + i;
#pragma unroll
        for (int j = 0; j < 4; j++) {
            int n = n0 + tx * 4 + j;
            if (n < Ntot) pbase[(long)m * Ntot + n] = acc[i][j];
        }
    }
}

// ============================ combo1: pack_W | pack_A | xq-gemm ============
#define NB_PW 2400                       // (1200*2048/4)/256
#define NB_PA (7 * 64 * 64)              // 28672
#define NB_XQ (19 * 8)                   // 152

__global__ void combo1(const float* __restrict__ Wv_att,
                       const float* __restrict__ V,
                       const float* __restrict__ input_q,
                       const float* __restrict__ Wq_att,
                       float* __restrict__ part_xq)
{
    __shared__ float smA[64][33];
    __shared__ float smB[64][33];
    const int id = blockIdx.x;
    if (id < NB_PW) {
        // ---- pack_W ----
        size_t i = (size_t)id * 256 + threadIdx.x;
        const float4 v = ((const float4*)Wv_att)[i];
        __nv_bfloat16 h0, l0, h1, l1, h2, l2, h3, l3;
        split_bf16(v.x, h0, l0); split_bf16(v.y, h1, l1);
        split_bf16(v.z, h2, l2); split_bf16(v.w, h3, l3);
        __nv_bfloat162* Hi = (__nv_bfloat162*)g_Bhi;
        __nv_bfloat162* Lo = (__nv_bfloat162*)g_Blo;
        Hi[i * 2 + 0] = __nv_bfloat162(h0, h1); Hi[i * 2 + 1] = __nv_bfloat162(h2, h3);
        Lo[i * 2 + 0] = __nv_bfloat162(l0, l1); Lo[i * 2 + 1] = __nv_bfloat162(l2, l3);
    } else if (id < NB_PW + NB_PA) {
        // ---- pack_A (transpose 32x32 via smem) ----
        float (*tile)[33] = smA;     // reuse 32x33 prefix
        int a   = id - NB_PW;
        int ns0 = (a % 7) * 32;
        int k0  = ((a / 7) % 64) * 32;
        int b   = a / 448;
        int tx = threadIdx.x & 31, ty = threadIdx.x >> 5;   // (32, 8)
#pragma unroll
        for (int r = 0; r < 4; r++) {
            int kl = ty + r * 8;
            int ns = ns0 + tx;
            float v = (ns < WH_) ? V[((size_t)b * DV_ + (k0 + kl)) * WH_ + ns] : 0.f;
            tile[kl][tx] = v;
        }
        __syncthreads();
#pragma unroll
        for (int r = 0; r < 4; r++) {
            int nsl = ty + r * 8;
            int ns = ns0 + nsl;
            if (ns < WH_) {
                size_t m = (size_t)b * WH_ + ns;
                float v = tile[tx][nsl];
                __nv_bfloat16 hi, lo;
                split_bf16(v, hi, lo);
                g_Ahi[m * DV_ + k0 + tx] = hi;
                g_Alo[m * DV_ + k0 + tx] = lo;
            }
        }
    } else {
        // ---- xq gemm partials ----
        int q  = id - NB_PW - NB_PA;
        int nt = q % 19, sp = q / 19;
        gemm64_body(input_q, Wq_att, part_xq, DA_, DQ_, DQ_, nt * 64, sp, 8, smA, smB);
    }
}

// ============================ GEMM1 (+ co-scheduled qfus) ==================
// gemm1: block 128x128x32, 8 warps (2m x 4n), 3-stage cp.async pipeline,
// 1 sync/stage, swizzled 128B rows (hi|lo), 2 CTAs/SM. Hot loop = R11 best.
// Epilogue contracts xatt vs Watt (G=2) -> wgt partials (xatt never stored).
// Blocks >= NT_G1 run the independent qfus split-K GEMM in the drain phase.
#define STAGE2 32768            // A 128*128 + B 128*128
#define OFF_B2 16384
#define NBUF   3
#define SMEM_G1 (NBUF * STAGE2) // 98304 -> 2 CTAs/SM

__global__ void __launch_bounds__(256, 2)
gemm1_qfus(const float* __restrict__ bias, const float* __restrict__ xq,
           const float* __restrict__ Watt, float* __restrict__ wgtp,
           const float* __restrict__ input_q, const float* __restrict__ Wq_fus,
           float* __restrict__ part_qf)
{
    extern __shared__ __align__(1024) char sm[];

    if (blockIdx.x >= NT_G1) {
        // ---- co-scheduled qfus GEMM (dispatches last -> fills drain) ----
        int q  = blockIdx.x - NT_G1;
        int nt = q % 38, sp = q / 38;
        float (*As)[33] = (float(*)[33])sm;
        float (*Bs)[33] = (float(*)[33])(sm + 64 * 33 * 4);
        gemm64_body(input_q, Wq_fus, part_qf, G_ * DH_, DQ_, DQ_, nt * 64, sp, 8, As, Bs);
        return;
    }

    const uint32_t sb = smem_u32(sm);
    const int tid = threadIdx.x, warp = tid >> 5, lane = tid & 31;
    const int m0 = (blockIdx.x / NBLK_N) * 128;
    const int n0 = (blockIdx.x % NBLK_N) * 128;
    const int wm = (warp & 1) * 64;
    const int wn = (warp >> 1) * 32;

    float acc[4][4][4];
#pragma unroll
    for (int mi = 0; mi < 4; mi++)
#pragma unroll
        for (int nf = 0; nf < 4; nf++)
#pragma unroll
            for (int e = 0; e < 4; e++) acc[mi][nf][e] = 0.f;

    const int r_a = tid >> 2, c_a = tid & 3;   // loader: row, 16B chunk

    auto load_stage = [&](int ks, int buf) {
        const int k0 = ks * 32;
        const uint32_t base = sb + buf * STAGE2;
#pragma unroll
        for (int part = 0; part < 2; part++) {
            const __nv_bfloat16* src = part ? g_Alo : g_Ahi;
#pragma unroll
            for (int i = 0; i < 2; i++) {
                int row = r_a + i * 64;
                uint32_t lg = row * 128 + part * 64 + c_a * 16;
                cp16(base + SWZ(lg),
                     src + (size_t)(m0 + row) * DV_ + k0 + c_a * 8);
            }
        }
#pragma unroll
        for (int part = 0; part < 2; part++) {
            const __nv_bfloat16* src = part ? g_Blo : g_Bhi;
#pragma unroll
            for (int i = 0; i < 2; i++) {
                int row = r_a + i * 64;
                int rg = n0 + row; if (rg >= DA_) rg = DA_ - 1;   // clamp
                uint32_t lg = OFF_B2 + row * 128 + part * 64 + c_a * 16;
                cp16(base + SWZ(lg),
                     src + (size_t)rg * DV_ + k0 + c_a * 8);
            }
        }
    };

    load_stage(0, 0); CP_COMMIT();
    load_stage(1, 1); CP_COMMIT();

    const int NST = DV_ / 32;   // 64
    for (int ks = 0; ks < NST; ks++) {
        const int buf = ks % NBUF;
        if (ks == NST - 1) { CP_WAIT(0); } else { CP_WAIT(1); }
        __syncthreads();

        const uint32_t base = sb + buf * STAGE2;
#pragma unroll
        for (int kb2 = 0; kb2 < 2; kb2++) {
            const int kb = kb2 * 16;
            uint32_t a_hi[4][4], a_lo[4][4];
            const uint32_t aLg = (wm + (lane & 15)) * 128 + kb * 2 + ((lane >> 4) << 4);
#pragma unroll
            for (int mi = 0; mi < 4; mi++) {
                ldsm_x4(a_hi[mi], base + SWZ(aLg + mi * 16 * 128));
                ldsm_x4(a_lo[mi], base + SWZ(aLg + mi * 16 * 128 + 64));
            }
            const uint32_t bLg = OFF_B2
                + (wn + ((lane >> 4) << 3) + (lane & 7)) * 128
                + (kb + ((lane >> 3) & 1) * 8) * 2;
#pragma unroll
            for (int nj = 0; nj < 2; nj++) {
                uint32_t b_hi[4], b_lo[4];
                ldsm_x4(b_hi, base + SWZ(bLg + nj * 16 * 128));
                ldsm_x4(b_lo, base + SWZ(bLg + nj * 16 * 128 + 64));
#pragma unroll
                for (int h = 0; h < 2; h++) {
                    const uint32_t* bh = &b_hi[h * 2];
                    const uint32_t* bl = &b_lo[h * 2];
                    const int nf = nj * 2 + h;
#pragma unroll
                    for (int mi = 0; mi < 4; mi++) {
                        mma_bf16(acc[mi][nf], a_hi[mi], bh);
                        mma_bf16(acc[mi][nf], a_hi[mi], bl);
                        mma_bf16(acc[mi][nf], a_lo[mi], bh);
                    }
                }
            }
        }
        if (ks + 2 < NST) { load_stage(ks + 2, (ks + 2) % NBUF); CP_COMMIT(); }
    }

    // ---- epilogue: xatt = tanh(tanh(acc+bias)*xq); contract vs Watt ----
    __syncthreads();      // all ldsm reads done before smem overlay
    float* wp = (float*)sm;               // [4 warpcol][128 rows][2 g]
    const int wcol = warp >> 1;

#pragma unroll
    for (int mi = 0; mi < 4; mi++) {
        const int r0 = m0 + wm + mi * 16 + (lane >> 2);
        const int r1 = r0 + 8;
        const int b0 = r0 / WH_, b1 = r1 / WH_;
        const float* xq0 = xq + (size_t)b0 * DA_;
        const float* xq1 = xq + (size_t)b1 * DA_;
        float p00 = 0.f, p01 = 0.f, p10 = 0.f, p11 = 0.f;  // [row0/1][g0/1]
#pragma unroll
        for (int nf = 0; nf < 4; nf++) {
            const int n = n0 + wn + nf * 8 + (lane & 3) * 2;
            if (n < DA_) {
                const float bz0 = bias[n], bz1 = bias[n + 1];
                const float w00 = Watt[n],        w01 = Watt[n + 1];
                const float w10 = Watt[DA_ + n],  w11 = Watt[DA_ + n + 1];
                float x00 = tanhf(tanhf(acc[mi][nf][0] + bz0) * xq0[n]);
                float x01 = tanhf(tanhf(acc[mi][nf][1] + bz1) * xq0[n + 1]);
                float x10 = tanhf(tanhf(acc[mi][nf][2] + bz0) * xq1[n]);
                float x11 = tanhf(tanhf(acc[mi][nf][3] + bz1) * xq1[n + 1]);
                p00 += x00 * w00 + x01 * w01;
                p01 += x00 * w10 + x01 * w11;
                p10 += x10 * w00 + x11 * w01;
                p11 += x10 * w10 + x11 * w11;
            }
        }
#pragma unroll
        for (int o = 1; o < 4; o <<= 1) {
            p00 += __shfl_xor_sync(0xffffffffu, p00, o);
            p01 += __shfl_xor_sync(0xffffffffu, p01, o);
            p10 += __shfl_xor_sync(0xffffffffu, p10, o);
            p11 += __shfl_xor_sync(0xffffffffu, p11, o);
        }
        if ((lane & 3) == 0) {
            int rl0 = wm + mi * 16 + (lane >> 2);
            wp[(wcol * 128 + rl0) * 2 + 0] = p00;
            wp[(wcol * 128 + rl0) * 2 + 1] = p01;
            wp[(wcol * 128 + rl0 + 8) * 2 + 0] = p10;
            wp[(wcol * 128 + rl0 + 8) * 2 + 1] = p11;
        }
    }
    __syncthreads();
    {
        int row = tid >> 1, g = tid & 1;
        float s = wp[(0 * 128 + row) * 2 + g] + wp[(1 * 128 + row) * 2 + g]
                + wp[(2 * 128 + row) * 2 + g] + wp[(3 * 128 + row) * 2 + g];
        wgtp[((size_t)(blockIdx.x % NBLK_N) * MROWS + m0 + row) * G_ + g] = s;
    }
}

// ---------------------------------------------------------------------------
// Fused: wgt = batt + sum_nblk wgtp (ordered); att = softmax(wgt).
// ---------------------------------------------------------------------------
__global__ void wgt_softmax(const float* __restrict__ wgtp,
                            const float* __restrict__ batt,
                            float* __restrict__ wgt_out,
                            float* __restrict__ att)
{
    __shared__ float red[256];
    int bg = blockIdx.x;               // 0..127
    int b = bg >> 1, g = bg & 1;
    int t = threadIdx.x;
    float v = -1e30f;
    if (t < WH_) {
        size_t m = (size_t)b * WH_ + t;
        float s = 0.f;
#pragma unroll
        for (int nb = 0; nb < NBLK_N; nb++)
            s += wgtp[((size_t)nb * MROWS + m) * G_ + g];
        v = s + batt[g];
        wgt_out[((size_t)b * G_ + g) * WH_ + t] = v;
    }
    red[t] = v; __syncthreads();
    for (int s2 = 128; s2 > 0; s2 >>= 1) {
        if (t < s2) red[t] = fmaxf(red[t], red[t + s2]);
        __syncthreads();
    }
    float mx = red[0]; __syncthreads();
    float e = (t < WH_) ? expf(v - mx) : 0.f;
    red[t] = e; __syncthreads();
    for (int s2 = 128; s2 > 0; s2 >>= 1) {
        if (t < s2) red[t] += red[t + s2];
        __syncthreads();
    }
    float inv = 1.f / red[0];
    if (t < WH_) att[((size_t)b * G_ + g) * WH_ + t] = e * inv;
}

// ---------------------------------------------------------------------------
// Standalone split-K small GEMM (for vfus and final), batched via blockIdx.z.
// ---------------------------------------------------------------------------
template<int SPLITS>
__global__ void gemm64s(const float* __restrict__ A,
                        const float* __restrict__ W,
                        float* __restrict__ part,
                        int Ntot, int K, int lda,
                        long aBS, long wBS)
{
    __shared__ float As[64][33];
    __shared__ float Bs[64][33];
    const int g = blockIdx.z;
    gemm64_body(A + (long)g * aBS, W + (long)g * wBS,
                part + (long)g * SPLITS * 64 * Ntot,
                Ntot, K, lda, blockIdx.x * 64, blockIdx.y, SPLITS, As, Bs);
}

// reduce split-K partials (ordered) + bias + activation. MODE 1: tanh; 3: id.
template<int MODE, int SPLITS>
__global__ void reduce_act(const float* __restrict__ part,
                           const float* __restrict__ bias,
                           float* __restrict__ C,
                           int Ntot, int ldc, long bBS, long cBS)
{
    const int g = blockIdx.y;
    int idx = blockIdx.x * blockDim.x + threadIdx.x;
    if (idx >= 64 * Ntot) return;
    int m = idx / Ntot, n = idx - m * Ntot;
    const float* pb = part + ((long)g * SPLITS * 64) * Ntot + (long)m * Ntot + n;
    float s = 0.f;
#pragma unroll
    for (int sp = 0; sp < SPLITS; sp++) s += pb[(long)sp * 64 * Ntot];
    float v = s + bias[(long)g * bBS + n];
    long co = (long)g * cBS + (long)m * ldc + n;
    C[co] = (MODE == 1) ? tanhf(v) : v;
}

// Merged: vfus = tanh(Σvf + bv); qf = tanh(Σqf + bq); hfus = vfus * qf.
// (vfus itself never materialized — it only feeds hfus.)
__global__ void reduce_vh(const float* __restrict__ part_vf,   // 2g x 8sp x 64 x 1200
                          const float* __restrict__ part_qf,   // 8sp x 64 x 2400
                          const float* __restrict__ bv_fus,    // [2,1200]
                          const float* __restrict__ bq_fus,    // [2400]
                          float* __restrict__ hfus)            // [64,2400]
{
    int idx = blockIdx.x * blockDim.x + threadIdx.x;
    if (idx >= 64 * G_ * DH_) return;
    int m = idx / (G_ * DH_), j = idx - m * (G_ * DH_);
    int g = j / DH_, n = j - g * DH_;
    const float* pv = part_vf + ((long)g * 8 * 64 + m) * DH_ + n;
    float sv = 0.f;
#pragma unroll
    for (int sp = 0; sp < 8; sp++) sv += pv[(long)sp * 64 * DH_];
    const float* pq = part_qf + (long)m * (G_ * DH_) + j;
    float sq = 0.f;
#pragma unroll
    for (int sp = 0; sp < 8; sp++) sq += pq[(long)sp * 64 * (G_ * DH_)];
    float v = tanhf(sv + bv_fus[(long)g * DH_ + n]);
    float q = tanhf(sq + bq_fus[j]);
    hfus[(long)m * (G_ * DH_) + j] = v * q;
}

// v_att[b,g,d] = sum_n att[b,g,n] * input_v[b,d,n]
__global__ void vatt_kernel(const float* __restrict__ v,
                            const float* __restrict__ att,
                            float* __restrict__ vatt)
{
    __shared__ float a0[WH_], a1[WH_];
    int b = blockIdx.x;
    int t = threadIdx.x;
    if (t < WH_) {
        a0[t] = att[((long)b * G_ + 0) * WH_ + t];
        a1[t] = att[((long)b * G_ + 1) * WH_ + t];
    }
    __syncthreads();
    int lane = t & 31, dd = t >> 5;
    int d = blockIdx.y * 8 + dd;
    const float* row = v + ((long)b * DV_ + d) * WH_;
    float s0 = 0.f, s1 = 0.f;
    for (int n = lane; n < WH_; n += 32) {
        float x = row[n];
        s0 += x * a0[n];
        s1 += x * a1[n];
    }
#pragma unroll
    for (int o = 16; o > 0; o >>= 1) {
        s0 += __shfl_down_sync(0xffffffffu, s0, o);
        s1 += __shfl_down_sync(0xffffffffu, s1, o);
    }
    if (lane == 0) {
        vatt[((long)b * G_ + 0) * DV_ + d] = s0;
        vatt[((long)b * G_ + 1) * DV_ + d] = s1;
    }
}

// ---------------------------------------------------------------------------
extern "C" void kernel_launch(void* const* d_in, const int* in_sizes, int n_in,
                              void* d_out, int out_size)
{
    const float* input_q = (const float*)d_in[0];
    const float* input_v = (const float*)d_in[1];
    const float* Wv_att  = (const float*)d_in[2];
    const float* bv_att  = (const float*)d_in[3];
    const float* Wq_att  = (const float*)d_in[4];
    const float* bq_att  = (const float*)d_in[5];
    const float* Watt    = (const float*)d_in[6];
    const float* batt    = (const float*)d_in[7];
    const float* Wv_fus  = (const float*)d_in[8];
    const float* bv_fus  = (const float*)d_in[9];
    const float* Wq_fus  = (const float*)d_in[10];
    const float* bq_fus  = (const float*)d_in[11];
    const float* Wc      = (const float*)d_in[12];
    const float* bc      = (const float*)d_in[13];

    float* out     = (float*)d_out;
    float* wgt_out = out + B_ * NC_;

    float *wgtp, *xq, *att, *vatt, *hfus, *partb;
    cudaGetSymbolAddress((void**)&wgtp, g_wgtp);
    cudaGetSymbolAddress((void**)&xq,   g_xq);
    cudaGetSymbolAddress((void**)&att,  g_att);
    cudaGetSymbolAddress((void**)&vatt, g_vatt);
    cudaGetSymbolAddress((void**)&hfus, g_hfus);
    cudaGetSymbolAddress((void**)&partb, g_part);

    cudaFuncSetAttribute(gemm1_qfus, cudaFuncAttributeMaxDynamicSharedMemorySize, SMEM_G1);

    // 1) pack_W | pack_A | xq-gemm (independent, one launch)
    combo1<<<NB_PW + NB_PA + NB_XQ, 256>>>(Wv_att, input_v, input_q, Wq_att,
                                           partb + P_XQ);

    // 2) xq = tanh(partials + bq_att)
    reduce_act<1, 8><<<dim3((64 * DA_ + 255) / 256, 1), 256>>>(
        partb + P_XQ, bq_att, xq, DA_, DA_, 0, 0);

    // 3) gemm1 (+wgt contraction) with qfus co-scheduled in the drain
    gemm1_qfus<<<NT_G1 + NB_QF, 256, SMEM_G1>>>(
        bv_att, xq, Watt, wgtp, input_q, Wq_fus, partb + P_QF);

    // 4) wgt reduce + softmax (fused)
    wgt_softmax<<<B_ * G_, 256>>>(wgtp, batt, wgt_out, att);

    // 5) v_att = att @ V
    vatt_kernel<<<dim3(B_, DV_ / 8), 256>>>(input_v, att, vatt);

    // 6) v_fus partials (batched g)
    gemm64s<8><<<dim3(19, 8, G_), 256>>>(
        vatt, Wv_fus, partb + P_VF, DH_, DV_, G_ * DV_, (long)DV_, (long)DH_ * DV_);

    // 7) hfus = tanh(vfus)*tanh(qfus)  (merged reduce, vfus never stored)
    reduce_vh<<<(64 * G_ * DH_ + 255) / 256, 256>>>(
        partb + P_VF, partb + P_QF, bv_fus, bq_fus, hfus);

    // 8,9) x = hfus @ Wc^T + bc
    gemm64s<8><<<dim3(47, 8, 1), 256>>>(hfus, Wc, partb, NC_, G_ * DH_, G_ * DH_, 0, 0);
    reduce_act<3, 8><<<dim3((64 * NC_ + 255) / 256, 1), 256>>>(
        partb, bc, out, NC_, NC_, 0, 0);
}

// round 16
// speedup vs baseline: 1.0575x; 1.0575x over previous
#include <cuda_runtime.h>
#include <cuda_bf16.h>
#include <math.h>
#include <cstdint>

// Problem dims
#define B_   64
#define DV_  2048
#define WH_  196
#define DQ_  2400
#define DA_  1200
#define G_   2
#define DH_  1200
#define NC_  3000
#define MROWS (B_*WH_)   // 12544
#define NBLK_N 10        // DA_/128 column blocks in gemm1

// ---------------- scratch (device globals; no allocation allowed) ----------
__device__ float g_wgtp[NBLK_N * MROWS * G_];   // wgt partials
__device__ float g_xq  [B_ * DA_];
__device__ float g_att [B_ * G_ * WH_];
__device__ float g_vatt[B_ * G_ * DV_];
__device__ float g_hfus[B_ * G_ * DH_];
__device__ float g_part[2 * 8 * 64 * NC_];      // split-K partials, carved:
#define P_XQ 0L                                  //  xq:   8*64*1200
#define P_QF (8L * 64 * 1200)                    //  qfus: 8*64*2400
#define P_VF (P_QF + 8L * 64 * 2400)             //  vfus: 16*64*1200
// final gemm reuses offset 0 (xq+qfus dead by then)
// bf16 split operands for GEMM1 (A = V transposed to [M,K] K-major)
__device__ __nv_bfloat16 g_Ahi[(size_t)MROWS * DV_];
__device__ __nv_bfloat16 g_Alo[(size_t)MROWS * DV_];
__device__ __nv_bfloat16 g_Bhi[(size_t)DA_ * DV_];
__device__ __nv_bfloat16 g_Blo[(size_t)DA_ * DV_];

// ============================ PTX helpers ==================================
__device__ __forceinline__ uint32_t smem_u32(const void* p) {
    uint32_t a;
    asm("{ .reg .u64 t; cvta.to.shared.u64 t, %1; cvt.u32.u64 %0, t; }" : "=r"(a) : "l"(p));
    return a;
}
__device__ __forceinline__ void cp16(uint32_t dst, const void* src) {
    asm volatile("cp.async.cg.shared.global [%0], [%1], 16;" :: "r"(dst), "l"(src));
}
#define CP_COMMIT() asm volatile("cp.async.commit_group;" ::: "memory")
#define CP_WAIT(n)  asm volatile("cp.async.wait_group %0;" :: "n"(n) : "memory")

__device__ __forceinline__ void ldsm_x4(uint32_t* r, uint32_t addr) {
    asm volatile("ldmatrix.sync.aligned.m8n8.x4.shared.b16 {%0,%1,%2,%3}, [%4];"
                 : "=r"(r[0]), "=r"(r[1]), "=r"(r[2]), "=r"(r[3]) : "r"(addr));
}
__device__ __forceinline__ void mma_bf16(float* c, const uint32_t* a, const uint32_t* b) {
    asm volatile("mma.sync.aligned.m16n8k16.row.col.f32.bf16.bf16.f32 "
                 "{%0,%1,%2,%3}, {%4,%5,%6,%7}, {%8,%9}, {%0,%1,%2,%3};"
                 : "+f"(c[0]), "+f"(c[1]), "+f"(c[2]), "+f"(c[3])
                 : "r"(a[0]), "r"(a[1]), "r"(a[2]), "r"(a[3]), "r"(b[0]), "r"(b[1]));
}
#define SWZ(bo) ((bo) ^ (((bo) >> 3) & 0x70))

// ============================ prepack kernels ==============================
__device__ __forceinline__ void split_bf16(float x, __nv_bfloat16& hi, __nv_bfloat16& lo) {
    hi = __float2bfloat16(x);
    lo = __float2bfloat16(x - __bfloat162float(hi));
}

__global__ void pack_W(const float* __restrict__ W) {
    size_t i = (size_t)blockIdx.x * blockDim.x + threadIdx.x;
    size_t total = (size_t)DA_ * DV_ / 4;
    if (i >= total) return;
    const float4 v = ((const float4*)W)[i];
    __nv_bfloat16 h0, l0, h1, l1, h2, l2, h3, l3;
    split_bf16(v.x, h0, l0); split_bf16(v.y, h1, l1);
    split_bf16(v.z, h2, l2); split_bf16(v.w, h3, l3);
    __nv_bfloat162* Hi = (__nv_bfloat162*)g_Bhi;
    __nv_bfloat162* Lo = (__nv_bfloat162*)g_Blo;
    Hi[i * 2 + 0] = __nv_bfloat162(h0, h1); Hi[i * 2 + 1] = __nv_bfloat162(h2, h3);
    Lo[i * 2 + 0] = __nv_bfloat162(l0, l1); Lo[i * 2 + 1] = __nv_bfloat162(l2, l3);
}

__global__ void pack_A(const float* __restrict__ V) {
    __shared__ float tile[32][33];
    int ns0 = blockIdx.x * 32;
    int k0  = blockIdx.y * 32;
    int b   = blockIdx.z;
    int tx = threadIdx.x, ty = threadIdx.y;   // (32, 8)
#pragma unroll
    for (int r = 0; r < 4; r++) {
        int kl = ty + r * 8;
        int ns = ns0 + tx;
        float v = (ns < WH_) ? V[((size_t)b * DV_ + (k0 + kl)) * WH_ + ns] : 0.f;
        tile[kl][tx] = v;
    }
    __syncthreads();
#pragma unroll
    for (int r = 0; r < 4; r++) {
        int nsl = ty + r * 8;
        int ns = ns0 + nsl;
        if (ns < WH_) {
            size_t m = (size_t)b * WH_ + ns;
            float v = tile[tx][nsl];
            __nv_bfloat16 hi, lo;
            split_bf16(v, hi, lo);
            g_Ahi[m * DV_ + k0 + tx] = hi;
            g_Alo[m * DV_ + k0 + tx] = lo;
        }
    }
}

// ============================ GEMM1 (mma.sync bf16, 3x split) ==============
// Block 128x128x32, 8 warps (2m x 4n), warp 64x32. 3-stage cp.async pipeline,
// 1 sync per stage, swizzled 128B rows (hi|lo) -> 2 CTAs per SM.
// Hot loop is byte-identical to the R11/R14 best (loads AFTER mma).
// Epilogue contracts xatt against Watt (G=2) -> wgt partials.
#define STAGE2 32768            // A 128*128 + B 128*128
#define OFF_B2 16384
#define NBUF   3
#define SMEM_G1 (NBUF * STAGE2) // 98304 -> 2 CTAs/SM

__global__ void __launch_bounds__(256, 2)
gemm1_mma(const float* __restrict__ bias, const float* __restrict__ xq,
          const float* __restrict__ Watt, float* __restrict__ wgtp)
{
    extern __shared__ __align__(1024) char sm[];
    const uint32_t sb = smem_u32(sm);
    const int tid = threadIdx.x, warp = tid >> 5, lane = tid & 31;
    const int m0 = blockIdx.y * 128;
    const int n0 = blockIdx.x * 128;
    const int wm = (warp & 1) * 64;
    const int wn = (warp >> 1) * 32;

    float acc[4][4][4];
#pragma unroll
    for (int mi = 0; mi < 4; mi++)
#pragma unroll
        for (int nf = 0; nf < 4; nf++)
#pragma unroll
            for (int e = 0; e < 4; e++) acc[mi][nf][e] = 0.f;

    const int r_a = tid >> 2, c_a = tid & 3;   // loader: row, 16B chunk

    auto load_stage = [&](int ks, int buf) {
        const int k0 = ks * 32;
        const uint32_t base = sb + buf * STAGE2;
#pragma unroll
        for (int part = 0; part < 2; part++) {
            const __nv_bfloat16* src = part ? g_Alo : g_Ahi;
#pragma unroll
            for (int i = 0; i < 2; i++) {
                int row = r_a + i * 64;
                uint32_t lg = row * 128 + part * 64 + c_a * 16;
                cp16(base + SWZ(lg),
                     src + (size_t)(m0 + row) * DV_ + k0 + c_a * 8);
            }
        }
#pragma unroll
        for (int part = 0; part < 2; part++) {
            const __nv_bfloat16* src = part ? g_Blo : g_Bhi;
#pragma unroll
            for (int i = 0; i < 2; i++) {
                int row = r_a + i * 64;
                int rg = n0 + row; if (rg >= DA_) rg = DA_ - 1;   // clamp
                uint32_t lg = OFF_B2 + row * 128 + part * 64 + c_a * 16;
                cp16(base + SWZ(lg),
                     src + (size_t)rg * DV_ + k0 + c_a * 8);
            }
        }
    };

    load_stage(0, 0); CP_COMMIT();
    load_stage(1, 1); CP_COMMIT();

    const int NST = DV_ / 32;   // 64
    for (int ks = 0; ks < NST; ks++) {
        const int buf = ks % NBUF;
        if (ks == NST - 1) { CP_WAIT(0); } else { CP_WAIT(1); }
        __syncthreads();

        const uint32_t base = sb + buf * STAGE2;
#pragma unroll
        for (int kb2 = 0; kb2 < 2; kb2++) {
            const int kb = kb2 * 16;
            uint32_t a_hi[4][4], a_lo[4][4];
            const uint32_t aLg = (wm + (lane & 15)) * 128 + kb * 2 + ((lane >> 4) << 4);
#pragma unroll
            for (int mi = 0; mi < 4; mi++) {
                ldsm_x4(a_hi[mi], base + SWZ(aLg + mi * 16 * 128));
                ldsm_x4(a_lo[mi], base + SWZ(aLg + mi * 16 * 128 + 64));
            }
            const uint32_t bLg = OFF_B2
                + (wn + ((lane >> 4) << 3) + (lane & 7)) * 128
                + (kb + ((lane >> 3) & 1) * 8) * 2;
#pragma unroll
            for (int nj = 0; nj < 2; nj++) {
                uint32_t b_hi[4], b_lo[4];
                ldsm_x4(b_hi, base + SWZ(bLg + nj * 16 * 128));
                ldsm_x4(b_lo, base + SWZ(bLg + nj * 16 * 128 + 64));
#pragma unroll
                for (int h = 0; h < 2; h++) {
                    const uint32_t* bh = &b_hi[h * 2];
                    const uint32_t* bl = &b_lo[h * 2];
                    const int nf = nj * 2 + h;
#pragma unroll
                    for (int mi = 0; mi < 4; mi++) {
                        mma_bf16(acc[mi][nf], a_hi[mi], bh);
                        mma_bf16(acc[mi][nf], a_hi[mi], bl);
                        mma_bf16(acc[mi][nf], a_lo[mi], bh);
                    }
                }
            }
        }
        if (ks + 2 < NST) { load_stage(ks + 2, (ks + 2) % NBUF); CP_COMMIT(); }
    }

    // ---- epilogue: xatt = tanh(tanh(acc+bias)*xq); contract vs Watt ----
    __syncthreads();      // all ldsm reads done before smem overlay
    float* wp = (float*)sm;               // [4 warpcol][128 rows][2 g]
    const int wcol = warp >> 1;

#pragma unroll
    for (int mi = 0; mi < 4; mi++) {
        const int r0 = m0 + wm + mi * 16 + (lane >> 2);
        const int r1 = r0 + 8;
        const int b0 = r0 / WH_, b1 = r1 / WH_;
        const float* xq0 = xq + (size_t)b0 * DA_;
        const float* xq1 = xq + (size_t)b1 * DA_;
        float p00 = 0.f, p01 = 0.f, p10 = 0.f, p11 = 0.f;  // [row0/1][g0/1]
#pragma unroll
        for (int nf = 0; nf < 4; nf++) {
            const int n = n0 + wn + nf * 8 + (lane & 3) * 2;
            if (n < DA_) {
                const float bz0 = bias[n], bz1 = bias[n + 1];
                const float w00 = Watt[n],        w01 = Watt[n + 1];
                const float w10 = Watt[DA_ + n],  w11 = Watt[DA_ + n + 1];
                float x00 = tanhf(tanhf(acc[mi][nf][0] + bz0) * xq0[n]);
                float x01 = tanhf(tanhf(acc[mi][nf][1] + bz1) * xq0[n + 1]);
                float x10 = tanhf(tanhf(acc[mi][nf][2] + bz0) * xq1[n]);
                float x11 = tanhf(tanhf(acc[mi][nf][3] + bz1) * xq1[n + 1]);
                p00 += x00 * w00 + x01 * w01;
                p01 += x00 * w10 + x01 * w11;
                p10 += x10 * w00 + x11 * w01;
                p11 += x10 * w10 + x11 * w11;
            }
        }
#pragma unroll
        for (int o = 1; o < 4; o <<= 1) {
            p00 += __shfl_xor_sync(0xffffffffu, p00, o);
            p01 += __shfl_xor_sync(0xffffffffu, p01, o);
            p10 += __shfl_xor_sync(0xffffffffu, p10, o);
            p11 += __shfl_xor_sync(0xffffffffu, p11, o);
        }
        if ((lane & 3) == 0) {
            int rl0 = wm + mi * 16 + (lane >> 2);
            wp[(wcol * 128 + rl0) * 2 + 0] = p00;
            wp[(wcol * 128 + rl0) * 2 + 1] = p01;
            wp[(wcol * 128 + rl0 + 8) * 2 + 0] = p10;
            wp[(wcol * 128 + rl0 + 8) * 2 + 1] = p11;
        }
    }
    __syncthreads();
    {
        int row = tid >> 1, g = tid & 1;
        float s = wp[(0 * 128 + row) * 2 + g] + wp[(1 * 128 + row) * 2 + g]
                + wp[(2 * 128 + row) * 2 + g] + wp[(3 * 128 + row) * 2 + g];
        wgtp[((size_t)blockIdx.x * MROWS + m0 + row) * G_ + g] = s;
    }
}

// ---------------------------------------------------------------------------
// Fused: wgt = batt + sum_nblk wgtp (ordered); att = softmax(wgt).
// ---------------------------------------------------------------------------
__global__ void wgt_softmax(const float* __restrict__ wgtp,
                            const float* __restrict__ batt,
                            float* __restrict__ wgt_out,
                            float* __restrict__ att)
{
    __shared__ float red[256];
    int bg = blockIdx.x;               // 0..127
    int b = bg >> 1, g = bg & 1;
    int t = threadIdx.x;
    float v = -1e30f;
    if (t < WH_) {
        size_t m = (size_t)b * WH_ + t;
        float s = 0.f;
#pragma unroll
        for (int nb = 0; nb < NBLK_N; nb++)
            s += wgtp[((size_t)nb * MROWS + m) * G_ + g];
        v = s + batt[g];
        wgt_out[((size_t)b * G_ + g) * WH_ + t] = v;
    }
    red[t] = v; __syncthreads();
    for (int s2 = 128; s2 > 0; s2 >>= 1) {
        if (t < s2) red[t] = fmaxf(red[t], red[t + s2]);
        __syncthreads();
    }
    float mx = red[0]; __syncthreads();
    float e = (t < WH_) ? expf(v - mx) : 0.f;
    red[t] = e; __syncthreads();
    for (int s2 = 128; s2 > 0; s2 >>= 1) {
        if (t < s2) red[t] += red[t + s2];
        __syncthreads();
    }
    float inv = 1.f / red[0];
    if (t < WH_) att[((size_t)b * G_ + g) * WH_ + t] = e * inv;
}

// ---------------------------------------------------------------------------
// Split-K small GEMM (M=64): 64x64 tile, BK=32, 256 threads, 4x4/thread.
// ---------------------------------------------------------------------------
template<int SPLITS>
__global__ void gemm64s(const float* __restrict__ A,
                        const float* __restrict__ W,
                        float* __restrict__ part,
                        int Ntot, int K, int lda,
                        long aBS, long wBS)
{
    const int g     = blockIdx.z;
    const int split = blockIdx.y;
    A += (long)g * aBS;
    W += (long)g * wBS;

    __shared__ float As[64][33];
    __shared__ float Bs[64][33];

    const int tid = threadIdx.x;
    const int ty  = tid >> 4;
    const int tx  = tid & 15;
    const int n0  = blockIdx.x * 64;
    const int lr  = tid >> 5;
    const int lk  = tid & 31;

    const int stages   = K / 32;
    const int st_begin = (stages * split) / SPLITS;
    const int st_end   = (stages * (split + 1)) / SPLITS;
    const int nst      = st_end - st_begin;

    auto fetchA = [&](int st, float* r) {
        int k0 = st * 32;
#pragma unroll
        for (int i = 0; i < 8; i++)
            r[i] = A[(long)(i * 8 + lr) * lda + k0 + lk];
    };
    auto fetchB = [&](int st, float* r) {
        int k0 = st * 32;
#pragma unroll
        for (int i = 0; i < 8; i++) {
            int ng = n0 + i * 8 + lr; if (ng >= Ntot) ng = Ntot - 1;
            r[i] = W[(long)ng * K + k0 + lk];
        }
    };

    float rA[2][8], rB[2][8];
    fetchA(st_begin, rA[0]); fetchB(st_begin, rB[0]);
    if (nst > 1) { fetchA(st_begin + 1, rA[1]); fetchB(st_begin + 1, rB[1]); }

    float acc[4][4];
#pragma unroll
    for (int i = 0; i < 4; i++)
#pragma unroll
        for (int j = 0; j < 4; j++) acc[i][j] = 0.f;

    for (int s = 0; s < nst; s++) {
        float* cA = rA[s & 1];
        float* cB = rB[s & 1];
        __syncthreads();
#pragma unroll
        for (int i = 0; i < 8; i++) {
            As[i * 8 + lr][lk] = cA[i];
            Bs[i * 8 + lr][lk] = cB[i];
        }
        if (s + 2 < nst) { fetchA(st_begin + s + 2, cA); fetchB(st_begin + s + 2, cB); }
        __syncthreads();
#pragma unroll
        for (int kk = 0; kk < 32; kk++) {
            float a[4], b[4];
#pragma unroll
            for (int i = 0; i < 4; i++) a[i] = As[ty * 4 + i][kk];
#pragma unroll
            for (int j = 0; j < 4; j++) b[j] = Bs[tx * 4 + j][kk];
#pragma unroll
            for (int i = 0; i < 4; i++)
#pragma unroll
                for (int j = 0; j < 4; j++) acc[i][j] += a[i] * b[j];
        }
    }

    float* pbase = part + ((long)(g * SPLITS + split) * 64) * Ntot;
#pragma unroll
    for (int i = 0; i < 4; i++) {
        int m = ty * 4 + i;
#pragma unroll
        for (int j = 0; j < 4; j++) {
            int n = n0 + tx * 4 + j;
            if (n < Ntot) pbase[(long)m * Ntot + n] = acc[i][j];
        }
    }
}

// reduce split-K partials (ordered) + bias + activation. MODE 1: tanh; 3: id.
template<int MODE, int SPLITS>
__global__ void reduce_act(const float* __restrict__ part,
                           const float* __restrict__ bias,
                           float* __restrict__ C,
                           int Ntot, int ldc, long bBS, long cBS)
{
    const int g = blockIdx.y;
    int idx = blockIdx.x * blockDim.x + threadIdx.x;
    if (idx >= 64 * Ntot) return;
    int m = idx / Ntot, n = idx - m * Ntot;
    const float* pb = part + ((long)g * SPLITS * 64) * Ntot + (long)m * Ntot + n;
    float s = 0.f;
#pragma unroll
    for (int sp = 0; sp < SPLITS; sp++) s += pb[(long)sp * 64 * Ntot];
    float v = s + bias[(long)g * bBS + n];
    long co = (long)g * cBS + (long)m * ldc + n;
    C[co] = (MODE == 1) ? tanhf(v) : v;
}

// Merged: vfus = tanh(Σvf + bv); qf = tanh(Σqf + bq); hfus = vfus * qf.
// (vfus never materialized — it only feeds hfus. Ordered sums, deterministic.)
__global__ void reduce_vh(const float* __restrict__ part_vf,   // [2g][8sp][64][1200]
                          const float* __restrict__ part_qf,   // [8sp][64][2400]
                          const float* __restrict__ bv_fus,    // [2,1200]
                          const float* __restrict__ bq_fus,    // [2400]
                          float* __restrict__ hfus)            // [64,2400]
{
    int idx = blockIdx.x * blockDim.x + threadIdx.x;
    if (idx >= 64 * G_ * DH_) return;
    int m = idx / (G_ * DH_), j = idx - m * (G_ * DH_);
    int g = j / DH_, n = j - g * DH_;
    const float* pv = part_vf + ((long)g * 8 * 64 + m) * DH_ + n;
    float sv = 0.f;
#pragma unroll
    for (int sp = 0; sp < 8; sp++) sv += pv[(long)sp * 64 * DH_];
    const float* pq = part_qf + (long)m * (G_ * DH_) + j;
    float sq = 0.f;
#pragma unroll
    for (int sp = 0; sp < 8; sp++) sq += pq[(long)sp * 64 * (G_ * DH_)];
    float v = tanhf(sv + bv_fus[(long)g * DH_ + n]);
    float q = tanhf(sq + bq_fus[j]);
    hfus[(long)m * (G_ * DH_) + j] = v * q;
}

// v_att[b,g,d] = sum_n att[b,g,n] * input_v[b,d,n]
__global__ void vatt_kernel(const float* __restrict__ v,
                            const float* __restrict__ att,
                            float* __restrict__ vatt)
{
    __shared__ float a0[WH_], a1[WH_];
    int b = blockIdx.x;
    int t = threadIdx.x;
    if (t < WH_) {
        a0[t] = att[((long)b * G_ + 0) * WH_ + t];
        a1[t] = att[((long)b * G_ + 1) * WH_ + t];
    }
    __syncthreads();
    int lane = t & 31, dd = t >> 5;
    int d = blockIdx.y * 8 + dd;
    const float* row = v + ((long)b * DV_ + d) * WH_;
    float s0 = 0.f, s1 = 0.f;
    for (int n = lane; n < WH_; n += 32) {
        float x = row[n];
        s0 += x * a0[n];
        s1 += x * a1[n];
    }
#pragma unroll
    for (int o = 16; o > 0; o >>= 1) {
        s0 += __shfl_down_sync(0xffffffffu, s0, o);
        s1 += __shfl_down_sync(0xffffffffu, s1, o);
    }
    if (lane == 0) {
        vatt[((long)b * G_ + 0) * DV_ + d] = s0;
        vatt[((long)b * G_ + 1) * DV_ + d] = s1;
    }
}

// ---------------------------------------------------------------------------
extern "C" void kernel_launch(void* const* d_in, const int* in_sizes, int n_in,
                              void* d_out, int out_size)
{
    const float* input_q = (const float*)d_in[0];
    const float* input_v = (const float*)d_in[1];
    const float* Wv_att  = (const float*)d_in[2];
    const float* bv_att  = (const float*)d_in[3];
    const float* Wq_att  = (const float*)d_in[4];
    const float* bq_att  = (const float*)d_in[5];
    const float* Watt    = (const float*)d_in[6];
    const float* batt    = (const float*)d_in[7];
    const float* Wv_fus  = (const float*)d_in[8];
    const float* bv_fus  = (const float*)d_in[9];
    const float* Wq_fus  = (const float*)d_in[10];
    const float* bq_fus  = (const float*)d_in[11];
    const float* Wc      = (const float*)d_in[12];
    const float* bc      = (const float*)d_in[13];

    float* out     = (float*)d_out;
    float* wgt_out = out + B_ * NC_;

    float *wgtp, *xq, *att, *vatt, *hfus, *partb;
    cudaGetSymbolAddress((void**)&wgtp, g_wgtp);
    cudaGetSymbolAddress((void**)&xq,   g_xq);
    cudaGetSymbolAddress((void**)&att,  g_att);
    cudaGetSymbolAddress((void**)&vatt, g_vatt);
    cudaGetSymbolAddress((void**)&hfus, g_hfus);
    cudaGetSymbolAddress((void**)&partb, g_part);

    cudaFuncSetAttribute(gemm1_mma, cudaFuncAttributeMaxDynamicSharedMemorySize, SMEM_G1);

    // 0,1) bf16 hi/lo prepack of GEMM1 operands
    pack_W<<<((size_t)DA_ * DV_ / 4 + 255) / 256, 256>>>(Wv_att);
    pack_A<<<dim3(7, DV_ / 32, B_), dim3(32, 8)>>>(input_v);

    // 2,3) xq = tanh(input_q @ Wq_att^T + bq_att)   [64, 1200]
    gemm64s<8><<<dim3(19, 8, 1), 256>>>(input_q, Wq_att, partb + P_XQ, DA_, DQ_, DQ_, 0, 0);
    reduce_act<1, 8><<<dim3((64 * DA_ + 255) / 256, 1), 256>>>(
        partb + P_XQ, bq_att, xq, DA_, DA_, 0, 0);

    // 4) q_fus partials (independent)
    gemm64s<8><<<dim3(38, 8, 1), 256>>>(input_q, Wq_fus, partb + P_QF, G_ * DH_, DQ_, DQ_, 0, 0);

    // 5) fused gemm1 + wgt contraction (xatt never materialized)
    gemm1_mma<<<dim3(NBLK_N, MROWS / 128), 256, SMEM_G1>>>(bv_att, xq, Watt, wgtp);

    // 6) wgt reduce + softmax (fused)
    wgt_softmax<<<B_ * G_, 256>>>(wgtp, batt, wgt_out, att);

    // 7) v_att = att @ V                          [64, 2, 2048]
    vatt_kernel<<<dim3(B_, DV_ / 8), 256>>>(input_v, att, vatt);

    // 8) v_fus partials (batched g)
    gemm64s<8><<<dim3(19, 8, G_), 256>>>(
        vatt, Wv_fus, partb + P_VF, DH_, DV_, G_ * DV_, (long)DV_, (long)DH_ * DV_);

    // 9) hfus = tanh(vfus)*tanh(qfus)  (merged reduce, vfus never stored)
    reduce_vh<<<(64 * G_ * DH_ + 255) / 256, 256>>>(
        partb + P_VF, partb + P_QF, bv_fus, bq_fus, hfus);

    // 10,11) x = hfus @ Wc^T + bc                 [64, 3000]
    gemm64s<8><<<dim3(47, 8, 1), 256>>>(hfus, Wc, partb, NC_, G_ * DH_, G_ * DH_, 0, 0);
    reduce_act<3, 8><<<dim3((64 * NC_ + 255) / 256, 1), 256>>>(
        partb, bc, out, NC_, NC_, 0, 0);
}